// round 13
// baseline (speedup 1.0000x reference)
#include <cuda_runtime.h>
#include <cuda_bf16.h>

#define NQ      65536
#define PP      2048
#define NREG    256                // 16x16 regions of 16px
#define NTHR    512
#define CAPC    384                // region candidates (mean ~136, >20 sigma)
#define LOG2E   1.4426950408889634f
#define THRESH  26.0f              // log2 cut: dropped mass <= 2048*2^-26 ~ 3e-5

// Static device state. g_tab fully rewritten each replay; barrier counters
// reset by the last-finishing CTA -> deterministic across graph replays.
__device__ float4   g_tab[256 * 256];        // 1 MB pixel table
__device__ unsigned g_arrive;
__device__ unsigned g_done;

__device__ __forceinline__ float ex2f(float x) {
    float r; asm("ex2.approx.f32 %0,%1;" : "=f"(r) : "f"(x)); return r;
}

// ---------------------------------------------------------------------------
// Single fused kernel. 256 CTAs x 512 thr, occ=2 (<=32 regs) => all CTAs
// co-resident => software grid barrier is deadlock-free.
//   Phase 0: prefetch this CTA's 256 queries (tid<256)
//   Phase 1: region cull (2048 -> ~130 cands, two-pass low-reg) +
//            per-pixel eval with 2 threads/pixel -> g_tab
//   Barrier
//   Phase 2: out[q] = g_tab[pixel(q)]
// ---------------------------------------------------------------------------
__global__ __launch_bounds__(NTHR, 2)
void k_all(const int2* __restrict__ X,
           const int2* __restrict__ pat,
           const float* __restrict__ W2,
           const float* __restrict__ sig,
           float* __restrict__ out) {
    __shared__ float4 cand[CAPC];        // {px, py, C, bitcast(p)}
    __shared__ float4 recA[CAPC];        // {A0, A1, B, C}
    __shared__ float4 recB[CAPC];        // {W0, W1, W2, 0}
    __shared__ float  wred[16];
    __shared__ int    wcnt[16];
    __shared__ int    s_nc;

    const int tid  = threadIdx.x;
    const int lane = tid & 31;
    const int wrp  = tid >> 5;
    const int r    = blockIdx.x;
    const int rx   = r >> 4, ry = r & 15;
    const float X0 = (float)(rx << 4), X1 = X0 + 15.0f;
    const float Y0 = (float)(ry << 4), Y1 = Y0 + 15.0f;

    // -- Phase 0: prefetch this CTA's queries (tid<256, held in regs) --
    int2 qxy = make_int2(0, 0);
    if (tid < 256) qxy = X[(r << 8) + tid];

    // -- Phase 1a pass 1: keep masks + region max bound (4 nodes/thread) --
    unsigned masks[4];
    float bestA = -1e30f;
#pragma unroll
    for (int k = 0; k < 4; k++) {
        int p = (k << 9) + tid;                        // coalesced
        int2 pp = pat[p];
        float px = (float)pp.x, py = (float)pp.y;
        float C = __fdividef(-0.5f * LOG2E, sig[p]);   // negative (MUFU rcp)
        float dxm = fmaxf(fabsf(px - X0), fabsf(px - X1));
        float dym = fmaxf(fabsf(py - Y0), fabsf(py - Y1));
        bestA = fmaxf(bestA, C * fmaf(dxm, dxm, dym * dym));
        float dxc = fmaxf(fmaxf(X0 - px, px - X1), 0.0f);
        float dyc = fmaxf(fmaxf(Y0 - py, py - Y1), 0.0f);
        // keep metric stashed via predicate after cut is known: store metric
        // in mask pass below (recomputed cheaply) -- here just stash masks=0
        masks[k] = __float_as_uint(C * fmaf(dxc, dxc, dyc * dyc)); // metric
    }
    for (int o = 16; o; o >>= 1)
        bestA = fmaxf(bestA, __shfl_xor_sync(0xffffffffu, bestA, o));
    if (lane == 0) wred[wrp] = bestA;
    __syncthreads();
    float cutA;
    {
        float b = wred[0];
#pragma unroll
        for (int w = 1; w < 16; w++) b = fmaxf(b, wred[w]);
        cutA = b - THRESH;
    }

    // ballots from stashed metrics (registers), count per warp
    int mycnt = 0;
#pragma unroll
    for (int k = 0; k < 4; k++) {
        unsigned m = __ballot_sync(0xffffffffu, __uint_as_float(masks[k]) >= cutA);
        masks[k] = m;
        mycnt += __popc(m);
    }
    if (lane == 0) wcnt[wrp] = mycnt;
    __syncthreads();
    int base = 0, total = 0;
#pragma unroll
    for (int w = 0; w < 16; w++) {
        if (w < wrp) base += wcnt[w];
        total += wcnt[w];
    }
    if (tid == 0) s_nc = total < CAPC ? total : CAPC;

    // -- Phase 1a pass 2: write kept candidates (reload pat/sig, L2-hot) --
#pragma unroll
    for (int k = 0; k < 4; k++) {
        unsigned m = masks[k];
        if ((m >> lane) & 1u) {
            int rk = base + __popc(m & ((1u << lane) - 1u));
            if (rk < CAPC) {
                int p = (k << 9) + tid;
                int2 pp = pat[p];
                float C = __fdividef(-0.5f * LOG2E, sig[p]);
                cand[rk] = make_float4((float)pp.x, (float)pp.y, C,
                                       __int_as_float(p));
            }
        }
        base += __popc(m);
    }
    __syncthreads();
    const int nc = s_nc;

    // -- Phase 1b: build eval records (parallel) --
    for (int i = tid; i < nc; i += NTHR) {
        float4 c = cand[i];
        int p = __float_as_int(c.w);
        float C = c.z;
        recA[i] = make_float4(-2.0f * C * c.x, -2.0f * C * c.y,
                              C * fmaf(c.x, c.x, c.y * c.y), C);
        recB[i] = make_float4(W2[p], W2[PP + p], W2[2 * PP + p], 0.0f);
    }
    __syncthreads();

    // -- Phase 1c: eval. 2 threads per pixel (even/odd candidates) --
    const int pix   = tid >> 1;              // 0..255
    const int chunk = tid & 1;
    const int ix = (rx << 4) + (pix >> 4);
    const int iy = (ry << 4) + (pix & 15);
    const float x0 = (float)ix, x1 = (float)iy;
    const float xx = fmaf(x0, x0, x1 * x1);

    float den = 0.f, n0 = 0.f, n1 = 0.f, n2 = 0.f;
#pragma unroll 4
    for (int j = chunk; j < nc; j += 2) {
        float4 a = recA[j];
        float4 b = recB[j];
        float arg = fmaf(a.w, xx, a.z);
        arg = fmaf(a.x, x0, arg);
        arg = fmaf(a.y, x1, arg);
        float e = ex2f(arg);
        den += e;
        n0 = fmaf(e, b.x, n0);
        n1 = fmaf(e, b.y, n1);
        n2 = fmaf(e, b.z, n2);
    }
    // pairwise combine (fixed order: even-half + odd-half) -> deterministic
    den += __shfl_xor_sync(0xffffffffu, den, 1);
    n0  += __shfl_xor_sync(0xffffffffu, n0, 1);
    n1  += __shfl_xor_sync(0xffffffffu, n1, 1);
    n2  += __shfl_xor_sync(0xffffffffu, n2, 1);
    if (chunk == 0) {
        float inv = 1.0f / den;
        g_tab[(ix << 8) + iy] = make_float4(n0 * inv, n1 * inv, n2 * inv, den);
    }

    // -- Grid barrier (all 256 CTAs resident by occupancy construction) --
    __syncthreads();
    if (tid == 0) {
        __threadfence();
        atomicAdd(&g_arrive, 1);
        while (*(volatile unsigned*)&g_arrive < NREG) {}
        __threadfence();
    }
    __syncthreads();

    // -- Phase 2: gather this CTA's prefetched queries --
    if (tid < 256) {
        float4 vq = g_tab[(qxy.x << 8) + qxy.y];
        int qidx = (r << 8) + tid;
        out[3 * qidx + 0] = vq.x;
        out[3 * qidx + 1] = vq.y;
        out[3 * qidx + 2] = vq.z;
    }

    // -- Epilogue: last CTA resets barrier state for the next replay --
    __syncthreads();
    if (tid == 0) {
        __threadfence();
        unsigned old = atomicAdd(&g_done, 1);
        if (old == NREG - 1) {
            g_arrive = 0;
            g_done = 0;
            __threadfence();
        }
    }
}

// ---------------------------------------------------------------------------
extern "C" void kernel_launch(void* const* d_in, const int* in_sizes, int n_in,
                              void* d_out, int out_size) {
    const int*   X   = (const int*)d_in[0];     // [N,2] int32
    const int*   pat = (const int*)d_in[1];     // [P,2] int32
    const float* W2  = (const float*)d_in[2];   // [C,P] f32
    const float* sig = (const float*)d_in[3];   // [P]   f32
    float* out = (float*)d_out;
    (void)in_sizes; (void)n_in; (void)out_size;

    k_all<<<NREG, NTHR>>>((const int2*)X, (const int2*)pat, W2, sig, out);
}

// round 14
// speedup vs baseline: 1.1443x; 1.1443x over previous
#include <cuda_runtime.h>
#include <cuda_bf16.h>

#define NQ      65536
#define PP      2048
#define NREG    256                // 16x16 regions of 16px
#define CAPC    384                // region candidates (mean ~136, >20 sigma)
#define LOG2E   1.4426950408889634f
#define THRESH  26.0f              // log2 cut: dropped mass <= 2048*2^-26 ~ 3e-5

// SMEM layout (dynamic, 61440 B):
//   fx   : CAPC*16 floats (24576 B)   fx[j*16+x] = ex2(C_j*(x-px)^2)
//   fy   : CAPC*16 floats (24576 B)
//   recB : CAPC float4   (6144 B)     {W0, W1, W2, 0}
//   cand : CAPC float4   (6144 B)     {px, py, C, bitcast(p)}
#define SMEM_BYTES 61440

// Pixel table, fully rewritten each replay -> stateless, deterministic.
__device__ float4 g_tab[256 * 256];

__device__ __forceinline__ float ex2f(float x) {
    float r; asm("ex2.approx.f32 %0,%1;" : "=f"(r) : "f"(x)); return r;
}

// ---------------------------------------------------------------------------
// K1: one CTA per 16x16 region. Proven cull (2048 -> ~130 cands), then
// separable tables fx/fy, then per-pixel eval = 1 FMUL + 4 FFMA per cand.
// ---------------------------------------------------------------------------
__global__ __launch_bounds__(256, 2)
void k_eval(const int2* __restrict__ pat,
            const float* __restrict__ W2,
            const float* __restrict__ sig) {
    extern __shared__ float sm[];
    float*  fx   = sm;                        // [CAPC*16]
    float*  fy   = sm + CAPC * 16;            // [CAPC*16]
    float4* recB = (float4*)(sm + 2 * CAPC * 16);   // [CAPC]
    float4* cand = recB + CAPC;               // [CAPC]
    __shared__ float wred[8];
    __shared__ int   wcnt[8];
    __shared__ int   s_nc;

    const int tid  = threadIdx.x;
    const int lane = tid & 31;
    const int wrp  = tid >> 5;
    const int r    = blockIdx.x;
    const int rx   = r >> 4, ry = r & 15;
    const float X0 = (float)(rx << 4), X1 = X0 + 15.0f;
    const float Y0 = (float)(ry << 4), Y1 = Y0 + 15.0f;

    // -- Level-A cull: 8 nodes/thread, region max bound + keep metric --
    float4 v[8];
    float keepm[8];
    float bestA = -1e30f;
#pragma unroll
    for (int k = 0; k < 8; k++) {
        int p = (k << 8) + tid;                        // coalesced
        int2 pp = pat[p];
        float px = (float)pp.x, py = (float)pp.y;
        float C = __fdividef(-0.5f * LOG2E, sig[p]);   // negative (MUFU rcp)
        float dxm = fmaxf(fabsf(px - X0), fabsf(px - X1));
        float dym = fmaxf(fabsf(py - Y0), fabsf(py - Y1));
        bestA = fmaxf(bestA, C * fmaf(dxm, dxm, dym * dym));
        float dxc = fmaxf(fmaxf(X0 - px, px - X1), 0.0f);
        float dyc = fmaxf(fmaxf(Y0 - py, py - Y1), 0.0f);
        keepm[k] = C * fmaf(dxc, dxc, dyc * dyc);
        v[k] = make_float4(px, py, C, __int_as_float(p));
    }
    for (int o = 16; o; o >>= 1)
        bestA = fmaxf(bestA, __shfl_xor_sync(0xffffffffu, bestA, o));
    if (lane == 0) wred[wrp] = bestA;
    __syncthreads();
    float cutA;
    {
        float b = wred[0];
#pragma unroll
        for (int w = 1; w < 8; w++) b = fmaxf(b, wred[w]);
        cutA = b - THRESH;
    }

    // -- Ballot compaction (warp-major, fixed ascending order) --
    int mycnt = 0;
    unsigned masks[8];
#pragma unroll
    for (int k = 0; k < 8; k++) {
        masks[k] = __ballot_sync(0xffffffffu, keepm[k] >= cutA);
        mycnt += __popc(masks[k]);
    }
    if (lane == 0) wcnt[wrp] = mycnt;
    __syncthreads();
    int base = 0, total = 0;
#pragma unroll
    for (int w = 0; w < 8; w++) {
        if (w < wrp) base += wcnt[w];
        total += wcnt[w];
    }
    if (tid == 0) s_nc = total < CAPC ? total : CAPC;
#pragma unroll
    for (int k = 0; k < 8; k++) {
        unsigned m = masks[k];
        if ((m >> lane) & 1u) {
            int rk = base + __popc(m & ((1u << lane) - 1u));
            if (rk < CAPC) cand[rk] = v[k];
        }
        base += __popc(m);
    }
    __syncthreads();
    const int nc = s_nc;

    // -- Build separable tables + weight records (parallel) --
    for (int i = tid; i < nc * 16; i += 256) {
        int j = i >> 4, o = i & 15;
        float4 c = cand[j];
        float dx = (X0 + (float)o) - c.x;
        float dy = (Y0 + (float)o) - c.y;
        fx[i] = ex2f(c.z * dx * dx);
        fy[i] = ex2f(c.z * dy * dy);
    }
    for (int j = tid; j < nc; j += 256) {
        int p = __float_as_int(cand[j].w);
        recB[j] = make_float4(W2[p], W2[PP + p], W2[2 * PP + p], 0.0f);
    }
    __syncthreads();

    // -- Eval: one pixel per thread; term = fx[j][tx] * fy[j][ty] --
    const int tx = tid >> 4, ty = tid & 15;
    float den = 0.f, n0 = 0.f, n1 = 0.f, n2 = 0.f;
#pragma unroll 4
    for (int j = 0; j < nc; j++) {
        float a = fx[(j << 4) + tx];         // 2 distinct addrs/warp
        float b = fy[(j << 4) + ty];         // 16 distinct, conflict-free
        float4 w = recB[j];                  // broadcast
        float t = a * b;
        den += t;
        n0 = fmaf(t, w.x, n0);
        n1 = fmaf(t, w.y, n1);
        n2 = fmaf(t, w.z, n2);
    }
    const int ix = (rx << 4) + tx;
    const int iy = (ry << 4) + ty;
    float inv = 1.0f / den;
    g_tab[(ix << 8) + iy] = make_float4(n0 * inv, n1 * inv, n2 * inv, den);
}

// ---------------------------------------------------------------------------
// K2: gather, 4 queries/thread (MLP=4), coalesced float4 stores.
// 128 CTAs x 128 thr = 16384 threads x 4 q.
// ---------------------------------------------------------------------------
__global__ __launch_bounds__(128)
void k_gather(const int4* __restrict__ X4, float4* __restrict__ out4) {
    int i = blockIdx.x * 128 + threadIdx.x;
    int4 a = X4[2 * i];
    int4 b = X4[2 * i + 1];
    float4 v0 = g_tab[(a.x << 8) + a.y];
    float4 v1 = g_tab[(a.z << 8) + a.w];
    float4 v2 = g_tab[(b.x << 8) + b.y];
    float4 v3 = g_tab[(b.z << 8) + b.w];
    out4[3 * i + 0] = make_float4(v0.x, v0.y, v0.z, v1.x);
    out4[3 * i + 1] = make_float4(v1.y, v1.z, v2.x, v2.y);
    out4[3 * i + 2] = make_float4(v2.z, v3.x, v3.y, v3.z);
}

// ---------------------------------------------------------------------------
extern "C" void kernel_launch(void* const* d_in, const int* in_sizes, int n_in,
                              void* d_out, int out_size) {
    const int*   X   = (const int*)d_in[0];     // [N,2] int32
    const int*   pat = (const int*)d_in[1];     // [P,2] int32
    const float* W2  = (const float*)d_in[2];   // [C,P] f32
    const float* sig = (const float*)d_in[3];   // [P]   f32
    float* out = (float*)d_out;
    (void)in_sizes; (void)n_in; (void)out_size;

    cudaFuncSetAttribute(k_eval,
                         cudaFuncAttributeMaxDynamicSharedMemorySize, SMEM_BYTES);
    k_eval<<<NREG, 256, SMEM_BYTES>>>((const int2*)pat, W2, sig);
    k_gather<<<128, 128>>>((const int4*)X, (float4*)out);
}